// round 11
// baseline (speedup 1.0000x reference)
#include <cuda_runtime.h>
#include <cuda_fp16.h>
#include <cstdint>

// KPConv, GB300 (sm_103a; harness compiles at compute_103 -> no tcgen05).
// Round 11: R9 + properly unrolled 2-deep pipeline (all compile-time indexing),
// points in registers (no ptile/cpa4), w-staging stride-10 + LDS.128 reads.

#define KP       15
#define FDIM     32
#define CDIM     64
#define KK       480
#define BM       32
#define THREADS  256
#define NSTEP    30
#define INV_EXTENT (1.0f / 0.6f)

#define ROW_STRIDE 976                    // 480 fp16 = 960B + 16B pad
#define A_BYTES    (BM * ROW_STRIDE)      // 31232
#define FBUF_BYTES 2048                   // 16 edges x 32 ch x 4B
#define BUFS_OFF   A_BYTES
#define SMEM_BYTES (BUFS_OFF + 8 * 2 * FBUF_BYTES)   // 64000 dynamic

__device__ uint4  g_bfrag[4 * NSTEP * 32];
__device__ int    g_rowptr[40001];

typedef unsigned long long ull;

__device__ __forceinline__ ull pack2f(float lo, float hi) {
    ull d; asm("mov.b64 %0, {%1, %2};" : "=l"(d) : "f"(lo), "f"(hi)); return d;
}
__device__ __forceinline__ void unpack2f(ull s, float& lo, float& hi) {
    asm("mov.b64 {%0, %1}, %2;" : "=f"(lo), "=f"(hi) : "l"(s));
}
__device__ __forceinline__ ull ffma2(ull a, ull b, ull c) {
    ull d; asm("fma.rn.f32x2 %0, %1, %2, %3;" : "=l"(d) : "l"(a), "l"(b), "l"(c)); return d;
}
__device__ __forceinline__ uint32_t smem_u32(const void* p) {
    uint32_t a;
    asm("{ .reg .u64 t; cvta.to.shared.u64 t, %1; cvt.u32.u64 %0, t; }" : "=r"(a) : "l"(p));
    return a;
}
__device__ __forceinline__ void ldsm4(uint32_t addr, uint32_t* r) {
    asm volatile("ldmatrix.sync.aligned.m8n8.x4.shared.b16 {%0,%1,%2,%3}, [%4];"
                 : "=r"(r[0]), "=r"(r[1]), "=r"(r[2]), "=r"(r[3]) : "r"(addr));
}
__device__ __forceinline__ void mma16816h(float* d, const uint32_t* a,
                                          uint32_t b0, uint32_t b1) {
    asm volatile(
        "mma.sync.aligned.m16n8k16.row.col.f32.f16.f16.f32 "
        "{%0,%1,%2,%3}, {%4,%5,%6,%7}, {%8,%9}, {%0,%1,%2,%3};"
        : "+f"(d[0]), "+f"(d[1]), "+f"(d[2]), "+f"(d[3])
        : "r"(a[0]), "r"(a[1]), "r"(a[2]), "r"(a[3]), "r"(b0), "r"(b1));
}
__device__ __forceinline__ void cpa16(uint32_t dst, const void* src) {
    asm volatile("cp.async.ca.shared.global [%0], [%1], 16;" :: "r"(dst), "l"(src));
}

// ================= prep: bfrag + rowptr =================
__global__ void prep_kernel(const float* __restrict__ kv,
                            const int* __restrict__ sid, int E, int M) {
    int b = blockIdx.x;
    int t = threadIdx.x;
    if (b == 0) {
        for (int i = t; i < 4 * NSTEP * 32; i += 256) {
            int l  = i & 31;
            int s  = (i >> 5) % NSTEP;
            int wn = i / (NSTEP * 32);
            int n0 = wn * 16 + (l >> 2);
            int kb = s * 16 + 2 * (l & 3);
            auto h2 = [&](int n, int k) -> uint32_t {
                __half2 p = __halves2half2(__float2half_rn(kv[k * CDIM + n]),
                                           __float2half_rn(kv[(k + 1) * CDIM + n]));
                return *(uint32_t*)&p;
            };
            uint4 v;
            v.x = h2(n0,     kb);
            v.y = h2(n0 + 8, kb);
            v.z = h2(n0,     kb + 8);
            v.w = h2(n0 + 8, kb + 8);
            g_bfrag[i] = v;
        }
    } else {
        int i = (b - 1) * 256 + t;
        if (i >= E) return;
        int s  = __ldg(sid + i);
        int sp = (i == 0) ? -1 : __ldg(sid + i - 1);
        for (int m = sp + 1; m <= s; m++) g_rowptr[m] = i;
        if (i == E - 1)
            for (int m = s + 1; m <= M; m++) g_rowptr[m] = E;
    }
}

// ================= main: pipelined fused agg + GEMM =================
__global__ __launch_bounds__(THREADS, 3) void kpconv_main_kernel(
    const float* __restrict__ points,
    const float* __restrict__ features,
    const float* __restrict__ outp,
    const int*   __restrict__ nbr,
    const float* __restrict__ kpts,
    float*       __restrict__ out,
    int M)
{
    extern __shared__ __align__(128) char sm[];   // A tile + feature double-buffers
    __shared__ ull   w2_s[8][160];                // [warp][edge*10], stride 10 (80B)
    __shared__ float kp[KP * 3];

    const uint32_t sbase = smem_u32(sm);
    const int tid  = threadIdx.x;
    const int warp = tid >> 5;
    const int lane = tid & 31;
    const int m0   = blockIdx.x * BM;

    if (tid < KP * 3) kp[tid] = kpts[tid];
    __syncthreads();

    ull* wrow = &w2_s[warp][0];
    const uint32_t fbuf0 = sbase + BUFS_OFF + warp * (2 * FBUF_BYTES);

    // row metadata (arrays only ever indexed with literal constants post-unroll)
    int s4[4], e4[4];
    float ox[4], oy[4], oz[4];
    #pragma unroll
    for (int rr = 0; rr < 4; rr++) {
        int m = m0 + warp + 8 * rr;
        if (m < M) {
            s4[rr] = __ldg(g_rowptr + m);
            e4[rr] = __ldg(g_rowptr + m + 1);
            ox[rr] = __ldg(outp + m * 3 + 0);
            oy[rr] = __ldg(outp + m * 3 + 1);
            oz[rr] = __ldg(outp + m * 3 + 2);
        } else { s4[rr] = 0; e4[rr] = 0; ox[rr] = oy[rr] = oz[rr] = 0.f; }
    }

    // prefetch: nbr LDG + own-point LDG (registers) + feature cp.async (1 group)
    auto prefetch = [&](int base, int cnt, uint32_t fb,
                        float& px, float& py, float& pz) {
        int my_ni = 0;
        if (lane < cnt) my_ni = __ldg(nbr + base + lane);
        px = 0.f; py = 0.f; pz = 0.f;
        if (lane < cnt) {
            const float* pp = points + (size_t)my_ni * 3;
            px = __ldg(pp); py = __ldg(pp + 1); pz = __ldg(pp + 2);
        }
        #pragma unroll
        for (int q = 0; q < 4; q++) {
            int t2 = q * 32 + lane;
            int edge = t2 >> 3, chunk = t2 & 7;
            int ni = __shfl_sync(0xffffffffu, my_ni, edge);   // uniform
            if (edge < cnt)
                cpa16(fb + (uint32_t)(edge * 32 + chunk * 4) * 4,
                      features + (size_t)ni * FDIM + chunk * 4);
        }
        asm volatile("cp.async.commit_group;");
    };

    ull acc2[8];
    #pragma unroll
    for (int p = 0; p < 8; p++) acc2[p] = 0ull;

    // consume: weight phase (points from regs) + FMA phase (LDS.128 w reads)
    auto consume = [&](int cnt, const float* ftile,
                       float oxv, float oyv, float ozv,
                       float px, float py, float pz) {
        float rx = px - oxv, ry = py - oyv, rz = pz - ozv;
        #pragma unroll
        for (int p = 0; p < 8; p++) {
            float w0, w1 = 0.f;
            {
                int k = 2 * p;
                float dx = rx - kp[k * 3 + 0];
                float dy = ry - kp[k * 3 + 1];
                float dz = rz - kp[k * 3 + 2];
                float sq = fmaf(dx, dx, fmaf(dy, dy, dz * dz));
                w0 = fmaxf(1.f - sqrtf(sq) * INV_EXTENT, 0.f);
            }
            if (p < 7) {
                int k = 2 * p + 1;
                float dx = rx - kp[k * 3 + 0];
                float dy = ry - kp[k * 3 + 1];
                float dz = rz - kp[k * 3 + 2];
                float sq = fmaf(dx, dx, fmaf(dy, dy, dz * dz));
                w1 = fmaxf(1.f - sqrtf(sq) * INV_EXTENT, 0.f);
            }
            if (lane < 16) wrow[lane * 10 + p] = pack2f(w0, w1);
        }
        __syncwarp();

        for (int j = 0; j < cnt; ++j) {
            float ft = ftile[j * 32 + lane];
            ull fd = pack2f(ft, ft);
            const ulonglong2* wj = (const ulonglong2*)(wrow + j * 10);
            ulonglong2 q0 = wj[0], q1 = wj[1], q2 = wj[2], q3 = wj[3];
            acc2[0] = ffma2(fd, q0.x, acc2[0]);
            acc2[1] = ffma2(fd, q0.y, acc2[1]);
            acc2[2] = ffma2(fd, q1.x, acc2[2]);
            acc2[3] = ffma2(fd, q1.y, acc2[3]);
            acc2[4] = ffma2(fd, q2.x, acc2[4]);
            acc2[5] = ffma2(fd, q2.y, acc2[5]);
            acc2[6] = ffma2(fd, q3.x, acc2[6]);
            acc2[7] = ffma2(fd, q3.y, acc2[7]);
        }
        __syncwarp();
    };

    // ---- pipelined, fully-unrolled row loop ----
    float cpx, cpy, cpz, npx, npy, npz;
    {
        int c0 = e4[0] - s4[0]; if (c0 > 16) c0 = 16; if (c0 < 0) c0 = 0;
        prefetch(s4[0], c0, fbuf0, cpx, cpy, cpz);
    }

    #pragma unroll
    for (int rr = 0; rr < 4; rr++) {
        const int s = s4[rr], e = e4[rr];
        int cnt = e - s; if (cnt > 16) cnt = 16; if (cnt < 0) cnt = 0;

        if (rr < 3) {
            int cN = e4[rr + 1] - s4[rr + 1];
            if (cN > 16) cN = 16; if (cN < 0) cN = 0;
            prefetch(s4[rr + 1], cN, fbuf0 + ((rr + 1) & 1) * FBUF_BYTES,
                     npx, npy, npz);
            asm volatile("cp.async.wait_group 1;");
        } else {
            asm volatile("cp.async.wait_group 0;");
        }
        __syncwarp();

        const float* ftile = (const float*)(sm + BUFS_OFF
                             + warp * (2 * FBUF_BYTES) + (rr & 1) * FBUF_BYTES);
        consume(cnt, ftile, ox[rr], oy[rr], oz[rr], cpx, cpy, cpz);

        // tail batches (rows with >16 edges; ~12% of rows)
        for (int base = s + 16; base < e; base += 16) {
            int c2 = e - base; if (c2 > 16) c2 = 16;
            float tpx, tpy, tpz;
            prefetch(base, c2, fbuf0 + (rr & 1) * FBUF_BYTES, tpx, tpy, tpz);
            asm volatile("cp.async.wait_group 0;");   // drains next-row group too (ok)
            __syncwarp();
            consume(c2, ftile, ox[rr], oy[rr], oz[rr], tpx, tpy, tpz);
        }

        // flush row rr accumulators to A tile (zeros for empty rows)
        {
            char* ar = sm + (warp + 8 * rr) * ROW_STRIDE;
            #pragma unroll
            for (int p = 0; p < 8; p++) {
                float v0, v1;
                unpack2f(acc2[p], v0, v1);
                int k0 = (2 * p) * 32 + lane;
                *(__half*)(ar + k0 * 2) = __float2half_rn(v0);
                if (p < 7) {
                    int k1 = (2 * p + 1) * 32 + lane;
                    *(__half*)(ar + k1 * 2) = __float2half_rn(v1);
                }
                acc2[p] = 0ull;
            }
        }
        cpx = npx; cpy = npy; cpz = npz;
    }
    __syncthreads();

    // ---------------- Phase B: GEMM [32,480] x [64,480]^T ----------------
    const int warp_m = warp & 1;
    const int warp_n = warp >> 1;
    const uint32_t abase = sbase + (uint32_t)(warp_m * 16 + (lane & 15)) * ROW_STRIDE
                         + (uint32_t)(lane >> 4) * 16;
    const uint4* bf = g_bfrag + (size_t)warp_n * NSTEP * 32 + lane;

    float acc[2][4];
    #pragma unroll
    for (int nt = 0; nt < 2; nt++)
        #pragma unroll
        for (int i = 0; i < 4; i++) acc[nt][i] = 0.f;

    #pragma unroll
    for (int s = 0; s < NSTEP; s++) {
        uint32_t a[4];
        ldsm4(abase + (uint32_t)s * 32, a);
        uint4 f = __ldg(bf + s * 32);
        mma16816h(acc[0], a, f.x, f.z);
        mma16816h(acc[1], a, f.y, f.w);
    }

    const int qr = lane >> 2;
    const int qc = (lane & 3) * 2;
    #pragma unroll
    for (int nt = 0; nt < 2; nt++) {
        int r0 = m0 + warp_m * 16 + qr;
        int cc = warp_n * 16 + nt * 8 + qc;
        if (r0 < M)
            *(float2*)(out + (size_t)r0 * CDIM + cc) = make_float2(acc[nt][0], acc[nt][1]);
        if (r0 + 8 < M)
            *(float2*)(out + (size_t)(r0 + 8) * CDIM + cc) = make_float2(acc[nt][2], acc[nt][3]);
    }
}

// ================= launch =================
extern "C" void kernel_launch(void* const* d_in, const int* in_sizes, int n_in,
                              void* d_out, int out_size) {
    const float* points   = (const float*)d_in[0];
    const float* features = (const float*)d_in[1];
    const float* outp     = (const float*)d_in[2];
    const int*   nbr      = (const int*)d_in[3];
    const int*   sid      = (const int*)d_in[4];
    const float* kpts     = (const float*)d_in[5];
    const float* kv       = (const float*)d_in[6];
    float*       out      = (float*)d_out;

    int E = in_sizes[3];
    int M = out_size / CDIM;

    static bool attr_set = false;
    if (!attr_set) {
        cudaFuncSetAttribute(kpconv_main_kernel,
                             cudaFuncAttributeMaxDynamicSharedMemorySize,
                             SMEM_BYTES);
        attr_set = true;
    }

    int prep_blocks = 1 + (E + 255) / 256;
    prep_kernel<<<prep_blocks, 256>>>(kv, sid, E, M);
    int blocks = (M + BM - 1) / BM;
    kpconv_main_kernel<<<blocks, THREADS, SMEM_BYTES>>>(
        points, features, outp, nbr, kpts, out, M);
}

// round 12
// speedup vs baseline: 1.2921x; 1.2921x over previous
#include <cuda_runtime.h>
#include <cuda_fp16.h>
#include <cstdint>

// KPConv, GB300 (sm_103a; harness compiles at compute_103 -> no tcgen05).
// Round 12: R9 (best, 71.8us) with two subtractive changes:
//  - points loaded into per-lane registers (ptile + cpa4 group deleted)
//  - __launch_bounds__(256,4): 4 CTAs/SM (issue-bound phase -> more warps)

#define KP       15
#define FDIM     32
#define CDIM     64
#define KK       480
#define BM       32
#define THREADS  256
#define NSTEP    30
#define INV_EXTENT (1.0f / 0.6f)

#define ROW_STRIDE 976                    // 480 fp16 = 960B + 16B pad
#define A_BYTES    (BM * ROW_STRIDE)      // 31232 (dynamic smem)

__device__ uint4  g_bfrag[4 * NSTEP * 32];   // [warp_n][step][lane]
__device__ int    g_rowptr[40001];

typedef unsigned long long ull;

__device__ __forceinline__ ull pack2f(float lo, float hi) {
    ull d; asm("mov.b64 %0, {%1, %2};" : "=l"(d) : "f"(lo), "f"(hi)); return d;
}
__device__ __forceinline__ void unpack2f(ull s, float& lo, float& hi) {
    asm("mov.b64 {%0, %1}, %2;" : "=f"(lo), "=f"(hi) : "l"(s));
}
__device__ __forceinline__ ull ffma2(ull a, ull b, ull c) {
    ull d; asm("fma.rn.f32x2 %0, %1, %2, %3;" : "=l"(d) : "l"(a), "l"(b), "l"(c)); return d;
}
__device__ __forceinline__ uint32_t smem_u32(const void* p) {
    uint32_t a;
    asm("{ .reg .u64 t; cvta.to.shared.u64 t, %1; cvt.u32.u64 %0, t; }" : "=r"(a) : "l"(p));
    return a;
}
__device__ __forceinline__ void ldsm4(uint32_t addr, uint32_t* r) {
    asm volatile("ldmatrix.sync.aligned.m8n8.x4.shared.b16 {%0,%1,%2,%3}, [%4];"
                 : "=r"(r[0]), "=r"(r[1]), "=r"(r[2]), "=r"(r[3]) : "r"(addr));
}
__device__ __forceinline__ void mma16816h(float* d, const uint32_t* a,
                                          uint32_t b0, uint32_t b1) {
    asm volatile(
        "mma.sync.aligned.m16n8k16.row.col.f32.f16.f16.f32 "
        "{%0,%1,%2,%3}, {%4,%5,%6,%7}, {%8,%9}, {%0,%1,%2,%3};"
        : "+f"(d[0]), "+f"(d[1]), "+f"(d[2]), "+f"(d[3])
        : "r"(a[0]), "r"(a[1]), "r"(a[2]), "r"(a[3]), "r"(b0), "r"(b1));
}
__device__ __forceinline__ void cpa16(uint32_t dst, const void* src) {
    asm volatile("cp.async.ca.shared.global [%0], [%1], 16;" :: "r"(dst), "l"(src));
}

// ================= prep: bfrag + rowptr =================
__global__ void prep_kernel(const float* __restrict__ kv,
                            const int* __restrict__ sid, int E, int M) {
    int b = blockIdx.x;
    int t = threadIdx.x;
    if (b == 0) {
        for (int i = t; i < 4 * NSTEP * 32; i += 256) {
            int l  = i & 31;
            int s  = (i >> 5) % NSTEP;
            int wn = i / (NSTEP * 32);
            int n0 = wn * 16 + (l >> 2);
            int kb = s * 16 + 2 * (l & 3);
            auto h2 = [&](int n, int k) -> uint32_t {
                __half2 p = __halves2half2(__float2half_rn(kv[k * CDIM + n]),
                                           __float2half_rn(kv[(k + 1) * CDIM + n]));
                return *(uint32_t*)&p;
            };
            uint4 v;
            v.x = h2(n0,     kb);
            v.y = h2(n0 + 8, kb);
            v.z = h2(n0,     kb + 8);
            v.w = h2(n0 + 8, kb + 8);
            g_bfrag[i] = v;
        }
    } else {
        int i = (b - 1) * 256 + t;
        if (i >= E) return;
        int s  = __ldg(sid + i);
        int sp = (i == 0) ? -1 : __ldg(sid + i - 1);
        for (int m = sp + 1; m <= s; m++) g_rowptr[m] = i;
        if (i == E - 1)
            for (int m = s + 1; m <= M; m++) g_rowptr[m] = E;
    }
}

// ================= main: fused agg + GEMM =================
__global__ __launch_bounds__(THREADS, 4) void kpconv_main_kernel(
    const float* __restrict__ points,
    const float* __restrict__ features,
    const float* __restrict__ outp,
    const int*   __restrict__ nbr,
    const float* __restrict__ kpts,
    float*       __restrict__ out,
    int M)
{
    extern __shared__ __align__(128) char sm[];          // A tile [32][976B]
    __shared__ ull   w2_s[8 * 8 * 16];                   // [warp][pair][edge]
    __shared__ float ftile_s[8][16][32];                 // per-warp feature tiles
    __shared__ float kp[KP * 3];

    const uint32_t sbase = smem_u32(sm);
    const int tid  = threadIdx.x;
    const int warp = tid >> 5;
    const int lane = tid & 31;
    const int m0   = blockIdx.x * BM;

    if (tid < KP * 3) kp[tid] = kpts[tid];
    __syncthreads();

    ull*   wrow  = w2_s + warp * 128;
    float* ftile = &ftile_s[warp][0][0];
    const uint32_t ftile_a = smem_u32(ftile);

    // ---------------- Phase A: aggregation, 4 rows per warp ----------------
    #pragma unroll
    for (int rr = 0; rr < 4; rr++) {
        const int r = warp + rr * 8;
        const int m = m0 + r;
        if (m < M) {
            int s = __ldg(g_rowptr + m);
            int e = __ldg(g_rowptr + m + 1);

            float ox = __ldg(outp + m * 3 + 0);
            float oy = __ldg(outp + m * 3 + 1);
            float oz = __ldg(outp + m * 3 + 2);

            ull acc2[8];
            #pragma unroll
            for (int p = 0; p < 8; p++) acc2[p] = 0ull;

            for (int base = s; base < e; base += 16) {
                int rem = e - base;
                int cnt = rem < 16 ? rem : 16;

                // nbr + own point into registers (lane = edge)
                int my_ni = 0;
                float px = 0.f, py = 0.f, pz = 0.f;
                if (lane < cnt) {
                    my_ni = __ldg(nbr + base + lane);
                    const float* pp = points + (size_t)my_ni * 3;
                    px = __ldg(pp); py = __ldg(pp + 1); pz = __ldg(pp + 2);
                }

                // feature rows via cp.async. SHFL UNIFORM, cp.async predicated.
                #pragma unroll
                for (int q = 0; q < 4; q++) {
                    int t2    = q * 32 + lane;
                    int edge  = t2 >> 3;          // 0..15
                    int chunk = t2 & 7;
                    int ni = __shfl_sync(0xffffffffu, my_ni, edge);   // uniform
                    if (edge < cnt)
                        cpa16(ftile_a + (edge * 32 + chunk * 4) * 4,
                              features + (size_t)ni * FDIM + chunk * 4);
                }
                asm volatile("cp.async.commit_group;");

                // --- weight phase: lane = edge, points from registers ---
                if (lane < 16) {
                    float rx = px - ox;
                    float ry = py - oy;
                    float rz = pz - oz;
                    #pragma unroll
                    for (int p = 0; p < 8; p++) {
                        float w0, w1 = 0.f;
                        {
                            int k = 2 * p;
                            float dx = rx - kp[k * 3 + 0];
                            float dy = ry - kp[k * 3 + 1];
                            float dz = rz - kp[k * 3 + 2];
                            float sq = fmaf(dx, dx, fmaf(dy, dy, dz * dz));
                            w0 = fmaxf(1.f - sqrtf(sq) * INV_EXTENT, 0.f);
                        }
                        if (p < 7) {
                            int k = 2 * p + 1;
                            float dx = rx - kp[k * 3 + 0];
                            float dy = ry - kp[k * 3 + 1];
                            float dz = rz - kp[k * 3 + 2];
                            float sq = fmaf(dx, dx, fmaf(dy, dy, dz * dz));
                            w1 = fmaxf(1.f - sqrtf(sq) * INV_EXTENT, 0.f);
                        }
                        wrow[p * 16 + lane] = pack2f(w0, w1);
                    }
                }

                // features ready
                asm volatile("cp.async.wait_group 0;");
                __syncwarp();

                // --- FMA phase: lane = feature channel, SMEM-only reads ---
                for (int j = 0; j < cnt; ++j) {
                    float ft = ftile[j * 32 + lane];
                    ull fd = pack2f(ft, ft);
                    #pragma unroll
                    for (int p = 0; p < 8; p++)
                        acc2[p] = ffma2(fd, wrow[p * 16 + j], acc2[p]);
                }
                __syncwarp();
            }

            // fp16 into resident SMEM A row
            char* ar = sm + r * ROW_STRIDE;
            #pragma unroll
            for (int p = 0; p < 8; p++) {
                float v0, v1;
                unpack2f(acc2[p], v0, v1);
                int k0 = (2 * p) * 32 + lane;
                *(__half*)(ar + k0 * 2) = __float2half_rn(v0);
                if (p < 7) {
                    int k1 = (2 * p + 1) * 32 + lane;
                    *(__half*)(ar + k1 * 2) = __float2half_rn(v1);
                }
            }
        }
    }
    __syncthreads();

    // ---------------- Phase B: GEMM [32,480] x [64,480]^T ----------------
    const int warp_m = warp & 1;
    const int warp_n = warp >> 1;
    const uint32_t abase = sbase + (uint32_t)(warp_m * 16 + (lane & 15)) * ROW_STRIDE
                         + (uint32_t)(lane >> 4) * 16;
    const uint4* bf = g_bfrag + (size_t)warp_n * NSTEP * 32 + lane;

    float acc[2][4];
    #pragma unroll
    for (int nt = 0; nt < 2; nt++)
        #pragma unroll
        for (int i = 0; i < 4; i++) acc[nt][i] = 0.f;

    #pragma unroll
    for (int s = 0; s < NSTEP; s++) {
        uint32_t a[4];
        ldsm4(abase + (uint32_t)s * 32, a);
        uint4 f = __ldg(bf + s * 32);
        mma16816h(acc[0], a, f.x, f.z);
        mma16816h(acc[1], a, f.y, f.w);
    }

    // epilogue (validated fragment mapping)
    const int qr = lane >> 2;
    const int qc = (lane & 3) * 2;
    #pragma unroll
    for (int nt = 0; nt < 2; nt++) {
        int r0 = m0 + warp_m * 16 + qr;
        int cc = warp_n * 16 + nt * 8 + qc;
        if (r0 < M)
            *(float2*)(out + (size_t)r0 * CDIM + cc) = make_float2(acc[nt][0], acc[nt][1]);
        if (r0 + 8 < M)
            *(float2*)(out + (size_t)(r0 + 8) * CDIM + cc) = make_float2(acc[nt][2], acc[nt][3]);
    }
}

// ================= launch =================
extern "C" void kernel_launch(void* const* d_in, const int* in_sizes, int n_in,
                              void* d_out, int out_size) {
    const float* points   = (const float*)d_in[0];
    const float* features = (const float*)d_in[1];
    const float* outp     = (const float*)d_in[2];
    const int*   nbr      = (const int*)d_in[3];
    const int*   sid      = (const int*)d_in[4];
    const float* kpts     = (const float*)d_in[5];
    const float* kv       = (const float*)d_in[6];
    float*       out      = (float*)d_out;

    int E = in_sizes[3];
    int M = out_size / CDIM;

    static bool attr_set = false;
    if (!attr_set) {
        cudaFuncSetAttribute(kpconv_main_kernel,
                             cudaFuncAttributeMaxDynamicSharedMemorySize,
                             A_BYTES);
        attr_set = true;
    }

    int prep_blocks = 1 + (E + 255) / 256;
    prep_kernel<<<prep_blocks, 256>>>(kv, sid, E, M);
    int blocks = (M + BM - 1) / BM;
    kpconv_main_kernel<<<blocks, THREADS, A_BYTES>>>(
        points, features, outp, nbr, kpts, out, M);
}

// round 13
// speedup vs baseline: 1.7740x; 1.3729x over previous
#include <cuda_runtime.h>
#include <cuda_fp16.h>
#include <cstdint>

// KPConv, GB300 (sm_103a; harness compiles at compute_103 -> no tcgen05).
// Round 13: aggregation AS tensor-core GEMM. Per 16-edge batch:
//   agg[16kp x 32f] += W^T[16x16] x F[16x32] via 4x mma.m16n8k16 (fp16 in,
//   fp32 accum) -- replaces 128 FFMA2 + 144 LDS per batch.
// Weight phase uses all 32 lanes (lane = edge + k-half), expanded-dot distances.
// Features pre-converted to fp16 (g_feat16): halves gather bytes too.
// Phase B (out GEMM) unchanged from R12 (validated).

#define KP       15
#define FDIM     32
#define CDIM     64
#define KK       480
#define BM       32
#define THREADS  256
#define NSTEP    30
#define INV_EXTENT (1.0f / 0.6f)

#define ROW_STRIDE 976                    // 480 fp16 = 960B + 16B pad
#define A_BYTES    (BM * ROW_STRIDE)      // 31232 (dynamic smem)

__device__ uint4  g_bfrag[4 * NSTEP * 32];
__device__ int    g_rowptr[40001];
__device__ __half g_feat16[40000 * FDIM];

__device__ __forceinline__ uint32_t smem_u32(const void* p) {
    uint32_t a;
    asm("{ .reg .u64 t; cvta.to.shared.u64 t, %1; cvt.u32.u64 %0, t; }" : "=r"(a) : "l"(p));
    return a;
}
__device__ __forceinline__ void ldsm4(uint32_t addr, uint32_t* r) {
    asm volatile("ldmatrix.sync.aligned.m8n8.x4.shared.b16 {%0,%1,%2,%3}, [%4];"
                 : "=r"(r[0]), "=r"(r[1]), "=r"(r[2]), "=r"(r[3]) : "r"(addr));
}
__device__ __forceinline__ void ldsm4t(uint32_t addr, uint32_t* r) {
    asm volatile("ldmatrix.sync.aligned.m8n8.x4.trans.shared.b16 {%0,%1,%2,%3}, [%4];"
                 : "=r"(r[0]), "=r"(r[1]), "=r"(r[2]), "=r"(r[3]) : "r"(addr));
}
__device__ __forceinline__ void mma16816h(float* d, const uint32_t* a,
                                          uint32_t b0, uint32_t b1) {
    asm volatile(
        "mma.sync.aligned.m16n8k16.row.col.f32.f16.f16.f32 "
        "{%0,%1,%2,%3}, {%4,%5,%6,%7}, {%8,%9}, {%0,%1,%2,%3};"
        : "+f"(d[0]), "+f"(d[1]), "+f"(d[2]), "+f"(d[3])
        : "r"(a[0]), "r"(a[1]), "r"(a[2]), "r"(a[3]), "r"(b0), "r"(b1));
}
__device__ __forceinline__ void cpa16(uint32_t dst, const void* src) {
    asm volatile("cp.async.ca.shared.global [%0], [%1], 16;" :: "r"(dst), "l"(src));
}

// ================= prep: bfrag + feat16 + rowptr =================
__global__ void prep_kernel(const float* __restrict__ kv,
                            const float* __restrict__ features,
                            const int* __restrict__ sid,
                            int E, int M, int NF, int nf16_blocks) {
    int b = blockIdx.x;
    int t = threadIdx.x;
    if (b == 0) {
        for (int i = t; i < 4 * NSTEP * 32; i += 256) {
            int l  = i & 31;
            int s  = (i >> 5) % NSTEP;
            int wn = i / (NSTEP * 32);
            int n0 = wn * 16 + (l >> 2);
            int kb = s * 16 + 2 * (l & 3);
            auto h2 = [&](int n, int k) -> uint32_t {
                __half2 p = __halves2half2(__float2half_rn(kv[k * CDIM + n]),
                                           __float2half_rn(kv[(k + 1) * CDIM + n]));
                return *(uint32_t*)&p;
            };
            uint4 v;
            v.x = h2(n0,     kb);
            v.y = h2(n0 + 8, kb);
            v.z = h2(n0,     kb + 8);
            v.w = h2(n0 + 8, kb + 8);
            g_bfrag[i] = v;
        }
    } else if (b <= nf16_blocks) {
        int i4 = ((b - 1) * 256 + t) * 4;
        if (i4 < NF) {
            float4 v = *(const float4*)(features + i4);
            __half2 h0 = __floats2half2_rn(v.x, v.y);
            __half2 h1 = __floats2half2_rn(v.z, v.w);
            *(uint2*)(g_feat16 + i4) = make_uint2(*(uint32_t*)&h0, *(uint32_t*)&h1);
        }
    } else {
        int i = (b - 1 - nf16_blocks) * 256 + t;
        if (i >= E) return;
        int s  = __ldg(sid + i);
        int sp = (i == 0) ? -1 : __ldg(sid + i - 1);
        for (int m = sp + 1; m <= s; m++) g_rowptr[m] = i;
        if (i == E - 1)
            for (int m = s + 1; m <= M; m++) g_rowptr[m] = E;
    }
}

// ================= main: fused agg(MMA) + GEMM =================
__global__ __launch_bounds__(THREADS, 4) void kpconv_main_kernel(
    const float* __restrict__ points,
    const float* __restrict__ outp,
    const int*   __restrict__ nbr,
    const float* __restrict__ kpts,
    float*       __restrict__ out,
    int M)
{
    extern __shared__ __align__(128) char sm[];         // A tile [32][976B]
    __shared__ __half w_s[8][16 * 16];                  // per-warp W[e][k]
    __shared__ __half f_s[8][16 * 32];                  // per-warp F[e][f] fp16
    __shared__ float4 kp4[16];                          // (x,y,z,|k|^2), k15 -> w=0

    const uint32_t sbase = smem_u32(sm);
    const int tid  = threadIdx.x;
    const int warp = tid >> 5;
    const int lane = tid & 31;
    const int m0   = blockIdx.x * BM;

    if (tid < 16) {
        if (tid < KP) {
            float x = kpts[tid * 3 + 0], y = kpts[tid * 3 + 1], z = kpts[tid * 3 + 2];
            kp4[tid] = make_float4(x, y, z, fmaf(x, x, fmaf(y, y, z * z)));
        } else {
            kp4[tid] = make_float4(0.f, 0.f, 0.f, 1.0e6f);   // forces w=0
        }
    }
    // zero this warp's feature tile (stale NaN protection for partial batches)
    {
        uint4* fz = (uint4*)&f_s[warp][0];
        fz[lane] = make_uint4(0, 0, 0, 0);
        fz[lane + 32] = make_uint4(0, 0, 0, 0);
    }
    __syncthreads();

    const uint32_t wbase = smem_u32(&w_s[warp][0]);
    const uint32_t fbase = smem_u32(&f_s[warp][0]);

    // ldmatrix lane addressing (precomputed)
    const int g  = lane >> 3;
    const int lr = lane & 7;
    // A = trans(W[e][k]):  g0:(e=lr,k0) g1:(e=lr,k8) g2:(e=lr+8,k0) g3:(e=lr+8,k8)
    const uint32_t a_addr = wbase + (uint32_t)(lr + ((g >> 1) << 3)) * 32
                          + (uint32_t)((g & 1) << 3) * 2;
    // B = trans(F[e][f]):  g0:(e=lr,f0) g1:(e=lr+8,f0) g2:(e=lr,f8) g3:(e=lr+8,f8)
    const uint32_t b_addr = fbase + (uint32_t)(lr + ((g & 1) << 3)) * 64
                          + (uint32_t)((g >> 1) << 3) * 2;

    const int eidx = lane & 15;           // edge for this lane
    const int khalf = lane >> 4;          // 0: k0-7, 1: k8-15
    const uint32_t wst = wbase + (uint32_t)eidx * 32 + (uint32_t)khalf * 16;

    // ---------------- Phase A: aggregation via MMA, 4 rows per warp ----------------
    #pragma unroll
    for (int rr = 0; rr < 4; rr++) {
        const int r = warp + rr * 8;
        const int m = m0 + r;
        if (m < M) {
            int s = __ldg(g_rowptr + m);
            int e = __ldg(g_rowptr + m + 1);

            float ox = __ldg(outp + m * 3 + 0);
            float oy = __ldg(outp + m * 3 + 1);
            float oz = __ldg(outp + m * 3 + 2);

            float ca[4][4];
            #pragma unroll
            for (int nb = 0; nb < 4; nb++)
                #pragma unroll
                for (int i = 0; i < 4; i++) ca[nb][i] = 0.f;

            for (int base = s; base < e; base += 16) {
                int rem = e - base;
                int cnt = rem < 16 ? rem : 16;
                bool valid = (eidx < cnt);

                // nbr + point (both half-warps load same edges; L1 dedups)
                int my_ni = 0;
                float px = 0.f, py = 0.f, pz = 0.f;
                if (valid) {
                    my_ni = __ldg(nbr + base + eidx);
                    const float* pp = points + (size_t)my_ni * 3;
                    px = __ldg(pp); py = __ldg(pp + 1); pz = __ldg(pp + 2);
                }

                // feature cp.async: lane's own edge, 2 chunks of 16B (fp16 rows)
                if (valid) {
                    const __half* srcf = g_feat16 + (size_t)my_ni * FDIM;
                    uint32_t dstf = fbase + (uint32_t)eidx * 64 + (uint32_t)khalf * 16;
                    cpa16(dstf,      srcf + khalf * 8);
                    cpa16(dstf + 32, srcf + 16 + khalf * 8);
                }
                asm volatile("cp.async.commit_group;");

                // ---- weight phase: 8 k-points per lane (expanded dot) ----
                float rx = px - ox, ry = py - oy, rz = pz - oz;
                float relsq = fmaf(rx, rx, fmaf(ry, ry, rz * rz));
                float w[8];
                #pragma unroll
                for (int kk = 0; kk < 8; kk++) {
                    float4 q = kp4[khalf * 8 + kk];
                    float d  = fmaf(rx, q.x, fmaf(ry, q.y, rz * q.z));
                    float sq = fmaxf(fmaf(-2.f, d, relsq + q.w), 0.f);
                    float wv = fmaxf(fmaf(sqrtf(sq), -INV_EXTENT, 1.f), 0.f);
                    w[kk] = valid ? wv : 0.f;
                }
                __half2 h0 = __floats2half2_rn(w[0], w[1]);
                __half2 h1 = __floats2half2_rn(w[2], w[3]);
                __half2 h2 = __floats2half2_rn(w[4], w[5]);
                __half2 h3 = __floats2half2_rn(w[6], w[7]);
                *(uint4*)(w_s[warp] + eidx * 16 + khalf * 8) =
                    make_uint4(*(uint32_t*)&h0, *(uint32_t*)&h1,
                               *(uint32_t*)&h2, *(uint32_t*)&h3);
                __syncwarp();

                // A fragment (W^T)
                uint32_t a[4];
                ldsm4t(a_addr, a);

                // features ready
                asm volatile("cp.async.wait_group 0;");
                __syncwarp();

                uint32_t b0[4], b1[4];
                ldsm4t(b_addr,      b0);    // n 0..15
                ldsm4t(b_addr + 32, b1);    // n 16..31

                mma16816h(ca[0], a, b0[0], b0[1]);
                mma16816h(ca[1], a, b0[2], b0[3]);
                mma16816h(ca[2], a, b1[0], b1[1]);
                mma16816h(ca[3], a, b1[2], b1[3]);
            }

            // flush agg fragments -> fp16 A-tile row (kk = kp*32 + f)
            char* ar = sm + r * ROW_STRIDE;
            const int kp1 = lane >> 2;
            const int f0  = (lane & 3) * 2;
            #pragma unroll
            for (int nb = 0; nb < 4; nb++) {
                int f = nb * 8 + f0;
                __half2 hA = __floats2half2_rn(ca[nb][0], ca[nb][1]);
                *(__half2*)(ar + (kp1 * 32 + f) * 2) = hA;
                if (kp1 < 7) {      // kp1+8 in 8..14 (kp15 padding row skipped)
                    __half2 hB = __floats2half2_rn(ca[nb][2], ca[nb][3]);
                    *(__half2*)(ar + ((kp1 + 8) * 32 + f) * 2) = hB;
                }
            }
        }
    }
    __syncthreads();

    // ---------------- Phase B: GEMM [32,480] x [64,480]^T (unchanged) ----------------
    const int warp_m = warp & 1;
    const int warp_n = warp >> 1;
    const uint32_t abase = sbase + (uint32_t)(warp_m * 16 + (lane & 15)) * ROW_STRIDE
                         + (uint32_t)(lane >> 4) * 16;
    const uint4* bf = g_bfrag + (size_t)warp_n * NSTEP * 32 + lane;

    float acc[2][4];
    #pragma unroll
    for (int nt = 0; nt < 2; nt++)
        #pragma unroll
        for (int i = 0; i < 4; i++) acc[nt][i] = 0.f;

    #pragma unroll
    for (int s = 0; s < NSTEP; s++) {
        uint32_t a[4];
        ldsm4(abase + (uint32_t)s * 32, a);
        uint4 f = __ldg(bf + s * 32);
        mma16816h(acc[0], a, f.x, f.z);
        mma16816h(acc[1], a, f.y, f.w);
    }

    const int qr = lane >> 2;
    const int qc = (lane & 3) * 2;
    #pragma unroll
    for (int nt = 0; nt < 2; nt++) {
        int r0 = m0 + warp_m * 16 + qr;
        int cc = warp_n * 16 + nt * 8 + qc;
        if (r0 < M)
            *(float2*)(out + (size_t)r0 * CDIM + cc) = make_float2(acc[nt][0], acc[nt][1]);
        if (r0 + 8 < M)
            *(float2*)(out + (size_t)(r0 + 8) * CDIM + cc) = make_float2(acc[nt][2], acc[nt][3]);
    }
}

// ================= launch =================
extern "C" void kernel_launch(void* const* d_in, const int* in_sizes, int n_in,
                              void* d_out, int out_size) {
    const float* points   = (const float*)d_in[0];
    const float* features = (const float*)d_in[1];
    const float* outp     = (const float*)d_in[2];
    const int*   nbr      = (const int*)d_in[3];
    const int*   sid      = (const int*)d_in[4];
    const float* kpts     = (const float*)d_in[5];
    const float* kv       = (const float*)d_in[6];
    float*       out      = (float*)d_out;

    int E  = in_sizes[3];
    int NF = in_sizes[1];
    int M  = out_size / CDIM;

    static bool attr_set = false;
    if (!attr_set) {
        cudaFuncSetAttribute(kpconv_main_kernel,
                             cudaFuncAttributeMaxDynamicSharedMemorySize,
                             A_BYTES);
        attr_set = true;
    }

    int nf16_blocks = (NF / 4 + 255) / 256;
    int prep_blocks = 1 + nf16_blocks + (E + 255) / 256;
    prep_kernel<<<prep_blocks, 256>>>(kv, features, sid, E, M, NF, nf16_blocks);
    int blocks = (M + BM - 1) / BM;
    kpconv_main_kernel<<<blocks, THREADS, A_BYTES>>>(
        points, outp, nbr, kpts, out, M);
}

// round 14
// speedup vs baseline: 1.8666x; 1.0522x over previous
#include <cuda_runtime.h>
#include <cuda_fp16.h>
#include <cstdint>

// KPConv, GB300 (sm_103a; harness compiles at compute_103 -> no tcgen05).
// Round 14: R13 (MMA aggregation, 52.3us) minus L1 wavefronts:
//  - g_pts4 float4 table: point gather = 1 LDG.128 (was 3 scattered LDG.32)
//  - kernel-point constants hoisted to registers (kq[8]), loaded once
//    (was 8 LDS.128 per batch); __launch_bounds__(256,3).

#define KP       15
#define FDIM     32
#define CDIM     64
#define KK       480
#define BM       32
#define THREADS  256
#define NSTEP    30
#define NPTS     40000
#define INV_EXTENT (1.0f / 0.6f)

#define ROW_STRIDE 976                    // 480 fp16 = 960B + 16B pad
#define A_BYTES    (BM * ROW_STRIDE)      // 31232 (dynamic smem)

__device__ uint4  g_bfrag[4 * NSTEP * 32];
__device__ int    g_rowptr[40001];
__device__ __half g_feat16[NPTS * FDIM];
__device__ float4 g_pts4[NPTS];

__device__ __forceinline__ uint32_t smem_u32(const void* p) {
    uint32_t a;
    asm("{ .reg .u64 t; cvta.to.shared.u64 t, %1; cvt.u32.u64 %0, t; }" : "=r"(a) : "l"(p));
    return a;
}
__device__ __forceinline__ void ldsm4(uint32_t addr, uint32_t* r) {
    asm volatile("ldmatrix.sync.aligned.m8n8.x4.shared.b16 {%0,%1,%2,%3}, [%4];"
                 : "=r"(r[0]), "=r"(r[1]), "=r"(r[2]), "=r"(r[3]) : "r"(addr));
}
__device__ __forceinline__ void ldsm4t(uint32_t addr, uint32_t* r) {
    asm volatile("ldmatrix.sync.aligned.m8n8.x4.trans.shared.b16 {%0,%1,%2,%3}, [%4];"
                 : "=r"(r[0]), "=r"(r[1]), "=r"(r[2]), "=r"(r[3]) : "r"(addr));
}
__device__ __forceinline__ void mma16816h(float* d, const uint32_t* a,
                                          uint32_t b0, uint32_t b1) {
    asm volatile(
        "mma.sync.aligned.m16n8k16.row.col.f32.f16.f16.f32 "
        "{%0,%1,%2,%3}, {%4,%5,%6,%7}, {%8,%9}, {%0,%1,%2,%3};"
        : "+f"(d[0]), "+f"(d[1]), "+f"(d[2]), "+f"(d[3])
        : "r"(a[0]), "r"(a[1]), "r"(a[2]), "r"(a[3]), "r"(b0), "r"(b1));
}
__device__ __forceinline__ void cpa16(uint32_t dst, const void* src) {
    asm volatile("cp.async.ca.shared.global [%0], [%1], 16;" :: "r"(dst), "l"(src));
}

// ================= prep: bfrag + feat16 + pts4 + rowptr =================
__global__ void prep_kernel(const float* __restrict__ kv,
                            const float* __restrict__ features,
                            const float* __restrict__ points,
                            const int* __restrict__ sid,
                            int E, int M, int NF,
                            int nf16_blocks, int pts_blocks) {
    int b = blockIdx.x;
    int t = threadIdx.x;
    if (b == 0) {
        for (int i = t; i < 4 * NSTEP * 32; i += 256) {
            int l  = i & 31;
            int s  = (i >> 5) % NSTEP;
            int wn = i / (NSTEP * 32);
            int n0 = wn * 16 + (l >> 2);
            int kb = s * 16 + 2 * (l & 3);
            auto h2 = [&](int n, int k) -> uint32_t {
                __half2 p = __halves2half2(__float2half_rn(kv[k * CDIM + n]),
                                           __float2half_rn(kv[(k + 1) * CDIM + n]));
                return *(uint32_t*)&p;
            };
            uint4 v;
            v.x = h2(n0,     kb);
            v.y = h2(n0 + 8, kb);
            v.z = h2(n0,     kb + 8);
            v.w = h2(n0 + 8, kb + 8);
            g_bfrag[i] = v;
        }
    } else if (b <= nf16_blocks) {
        int i4 = ((b - 1) * 256 + t) * 4;
        if (i4 < NF) {
            float4 v = *(const float4*)(features + i4);
            __half2 h0 = __floats2half2_rn(v.x, v.y);
            __half2 h1 = __floats2half2_rn(v.z, v.w);
            *(uint2*)(g_feat16 + i4) = make_uint2(*(uint32_t*)&h0, *(uint32_t*)&h1);
        }
    } else if (b <= nf16_blocks + pts_blocks) {
        int i = (b - 1 - nf16_blocks) * 256 + t;
        if (i < NPTS)
            g_pts4[i] = make_float4(points[i * 3], points[i * 3 + 1],
                                    points[i * 3 + 2], 0.f);
    } else {
        int i = (b - 1 - nf16_blocks - pts_blocks) * 256 + t;
        if (i >= E) return;
        int s  = __ldg(sid + i);
        int sp = (i == 0) ? -1 : __ldg(sid + i - 1);
        for (int m = sp + 1; m <= s; m++) g_rowptr[m] = i;
        if (i == E - 1)
            for (int m = s + 1; m <= M; m++) g_rowptr[m] = E;
    }
}

// ================= main: fused agg(MMA) + GEMM =================
__global__ __launch_bounds__(THREADS, 3) void kpconv_main_kernel(
    const float* __restrict__ outp,
    const int*   __restrict__ nbr,
    const float* __restrict__ kpts,
    float*       __restrict__ out,
    int M)
{
    extern __shared__ __align__(128) char sm[];         // A tile [32][976B]
    __shared__ __half w_s[8][16 * 16];                  // per-warp W[e][k]
    __shared__ __half f_s[8][16 * 32];                  // per-warp F[e][f] fp16

    const uint32_t sbase = smem_u32(sm);
    const int tid  = threadIdx.x;
    const int warp = tid >> 5;
    const int lane = tid & 31;
    const int m0   = blockIdx.x * BM;

    const int eidx  = lane & 15;          // edge for this lane
    const int khalf = lane >> 4;          // 0: k0-7, 1: k8-15

    // kernel-point constants in registers (row/batch-invariant)
    float4 kq[8];
    #pragma unroll
    for (int kk = 0; kk < 8; kk++) {
        int k = khalf * 8 + kk;
        if (k < KP) {
            float x = __ldg(kpts + k * 3 + 0);
            float y = __ldg(kpts + k * 3 + 1);
            float z = __ldg(kpts + k * 3 + 2);
            kq[kk] = make_float4(x, y, z, fmaf(x, x, fmaf(y, y, z * z)));
        } else {
            kq[kk] = make_float4(0.f, 0.f, 0.f, 1.0e6f);   // k15 -> w = 0
        }
    }

    // zero this warp's feature tile (stale-data protection for partial batches)
    {
        uint4* fz = (uint4*)&f_s[warp][0];
        fz[lane] = make_uint4(0, 0, 0, 0);
        fz[lane + 32] = make_uint4(0, 0, 0, 0);
    }
    __syncwarp();

    const uint32_t wbase = smem_u32(&w_s[warp][0]);
    const uint32_t fbase = smem_u32(&f_s[warp][0]);

    // ldmatrix lane addressing (validated R13 mapping)
    const int g  = lane >> 3;
    const int lr = lane & 7;
    const uint32_t a_addr = wbase + (uint32_t)(lr + ((g >> 1) << 3)) * 32
                          + (uint32_t)((g & 1) << 3) * 2;
    const uint32_t b_addr = fbase + (uint32_t)(lr + ((g & 1) << 3)) * 64
                          + (uint32_t)((g >> 1) << 3) * 2;

    // ---------------- Phase A: aggregation via MMA, 4 rows per warp ----------------
    #pragma unroll
    for (int rr = 0; rr < 4; rr++) {
        const int r = warp + rr * 8;
        const int m = m0 + r;
        if (m < M) {
            int s = __ldg(g_rowptr + m);
            int e = __ldg(g_rowptr + m + 1);

            float ox = __ldg(outp + m * 3 + 0);
            float oy = __ldg(outp + m * 3 + 1);
            float oz = __ldg(outp + m * 3 + 2);

            float ca[4][4];
            #pragma unroll
            for (int nb = 0; nb < 4; nb++)
                #pragma unroll
                for (int i = 0; i < 4; i++) ca[nb][i] = 0.f;

            for (int base = s; base < e; base += 16) {
                int rem = e - base;
                int cnt = rem < 16 ? rem : 16;
                bool valid = (eidx < cnt);

                // nbr + point via float4 table (1 LDG.128)
                int my_ni = 0;
                float px = 0.f, py = 0.f, pz = 0.f;
                if (valid) {
                    my_ni = __ldg(nbr + base + eidx);
                    float4 p = __ldg(&g_pts4[my_ni]);
                    px = p.x; py = p.y; pz = p.z;
                }

                // feature cp.async: lane's own edge, 2 chunks of 16B (fp16 rows)
                if (valid) {
                    const __half* srcf = g_feat16 + (size_t)my_ni * FDIM;
                    uint32_t dstf = fbase + (uint32_t)eidx * 64 + (uint32_t)khalf * 16;
                    cpa16(dstf,      srcf + khalf * 8);
                    cpa16(dstf + 32, srcf + 16 + khalf * 8);
                }
                asm volatile("cp.async.commit_group;");

                // ---- weight phase: 8 k-points per lane (expanded dot, kq regs) ----
                float rx = px - ox, ry = py - oy, rz = pz - oz;
                float relsq = fmaf(rx, rx, fmaf(ry, ry, rz * rz));
                float w[8];
                #pragma unroll
                for (int kk = 0; kk < 8; kk++) {
                    float4 q = kq[kk];
                    float d  = fmaf(rx, q.x, fmaf(ry, q.y, rz * q.z));
                    float sq = fmaxf(fmaf(-2.f, d, relsq + q.w), 0.f);
                    float wv = fmaxf(fmaf(sqrtf(sq), -INV_EXTENT, 1.f), 0.f);
                    w[kk] = valid ? wv : 0.f;
                }
                __half2 h0 = __floats2half2_rn(w[0], w[1]);
                __half2 h1 = __floats2half2_rn(w[2], w[3]);
                __half2 h2 = __floats2half2_rn(w[4], w[5]);
                __half2 h3 = __floats2half2_rn(w[6], w[7]);
                *(uint4*)(w_s[warp] + eidx * 16 + khalf * 8) =
                    make_uint4(*(uint32_t*)&h0, *(uint32_t*)&h1,
                               *(uint32_t*)&h2, *(uint32_t*)&h3);
                __syncwarp();

                // A fragment (W^T)
                uint32_t a[4];
                ldsm4t(a_addr, a);

                // features ready
                asm volatile("cp.async.wait_group 0;");
                __syncwarp();

                uint32_t b0[4], b1[4];
                ldsm4t(b_addr,      b0);    // f 0..15
                ldsm4t(b_addr + 32, b1);    // f 16..31

                mma16816h(ca[0], a, b0[0], b0[1]);
                mma16816h(ca[1], a, b0[2], b0[3]);
                mma16816h(ca[2], a, b1[0], b1[1]);
                mma16816h(ca[3], a, b1[2], b1[3]);
            }

            // flush agg fragments -> fp16 A-tile row (kk = kp*32 + f)
            char* ar = sm + r * ROW_STRIDE;
            const int kp1 = lane >> 2;
            const int f0  = (lane & 3) * 2;
            #pragma unroll
            for (int nb = 0; nb < 4; nb++) {
                int f = nb * 8 + f0;
                __half2 hA = __floats2half2_rn(ca[nb][0], ca[nb][1]);
                *(__half2*)(ar + (kp1 * 32 + f) * 2) = hA;
                if (kp1 < 7) {
                    __half2 hB = __floats2half2_rn(ca[nb][2], ca[nb][3]);
                    *(__half2*)(ar + ((kp1 + 8) * 32 + f) * 2) = hB;
                }
            }
        }
    }
    __syncthreads();

    // ---------------- Phase B: GEMM [32,480] x [64,480]^T (unchanged) ----------------
    const int warp_m = warp & 1;
    const int warp_n = warp >> 1;
    const uint32_t abase = sbase + (uint32_t)(warp_m * 16 + (lane & 15)) * ROW_STRIDE
                         + (uint32_t)(lane >> 4) * 16;
    const uint4* bf = g_bfrag + (size_t)warp_n * NSTEP * 32 + lane;

    float acc[2][4];
    #pragma unroll
    for (int nt = 0; nt < 2; nt++)
        #pragma unroll
        for (int i = 0; i < 4; i++) acc[nt][i] = 0.f;

    #pragma unroll
    for (int s = 0; s < NSTEP; s++) {
        uint32_t a[4];
        ldsm4(abase + (uint32_t)s * 32, a);
        uint4 f = __ldg(bf + s * 32);
        mma16816h(acc[0], a, f.x, f.z);
        mma16816h(acc[1], a, f.y, f.w);
    }

    const int qr = lane >> 2;
    const int qc = (lane & 3) * 2;
    #pragma unroll
    for (int nt = 0; nt < 2; nt++) {
        int r0 = m0 + warp_m * 16 + qr;
        int cc = warp_n * 16 + nt * 8 + qc;
        if (r0 < M)
            *(float2*)(out + (size_t)r0 * CDIM + cc) = make_float2(acc[nt][0], acc[nt][1]);
        if (r0 + 8 < M)
            *(float2*)(out + (size_t)(r0 + 8) * CDIM + cc) = make_float2(acc[nt][2], acc[nt][3]);
    }
}

// ================= launch =================
extern "C" void kernel_launch(void* const* d_in, const int* in_sizes, int n_in,
                              void* d_out, int out_size) {
    const float* points   = (const float*)d_in[0];
    const float* features = (const float*)d_in[1];
    const float* outp     = (const float*)d_in[2];
    const int*   nbr      = (const int*)d_in[3];
    const int*   sid      = (const int*)d_in[4];
    const float* kpts     = (const float*)d_in[5];
    const float* kv       = (const float*)d_in[6];
    float*       out      = (float*)d_out;

    int E  = in_sizes[3];
    int NF = in_sizes[1];
    int M  = out_size / CDIM;

    static bool attr_set = false;
    if (!attr_set) {
        cudaFuncSetAttribute(kpconv_main_kernel,
                             cudaFuncAttributeMaxDynamicSharedMemorySize,
                             A_BYTES);
        attr_set = true;
    }

    int nf16_blocks = (NF / 4 + 255) / 256;
    int pts_blocks  = (NPTS + 255) / 256;
    int prep_blocks = 1 + nf16_blocks + pts_blocks + (E + 255) / 256;
    prep_kernel<<<prep_blocks, 256>>>(kv, features, points, sid, E, M, NF,
                                      nf16_blocks, pts_blocks);
    int blocks = (M + BM - 1) / BM;
    kpconv_main_kernel<<<blocks, THREADS, A_BYTES>>>(outp, nbr, kpts, out, M);
}

// round 15
// speedup vs baseline: 2.0358x; 1.0907x over previous
#include <cuda_runtime.h>
#include <cuda_fp16.h>
#include <cstdint>

// KPConv, GB300 (sm_103a; harness compiles at compute_103 -> no tcgen05).
// Round 15: R14 with conflict-free SMEM strides in the aggregation tiles.
//  - f_s row stride 64B -> 80B  (kills 8-way cp.async write conflicts and
//    2-way ldmatrix.trans read conflicts)
//  - w_s row stride 32B -> 48B  (kills ldmatrix/STS conflicts)
// No other changes vs R14 (49.7us).

#define KP       15
#define FDIM     32
#define CDIM     64
#define KK       480
#define BM       32
#define THREADS  256
#define NSTEP    30
#define NPTS     40000
#define INV_EXTENT (1.0f / 0.6f)

#define ROW_STRIDE 976                    // 480 fp16 = 960B + 16B pad (mod-128-walk ok)
#define A_BYTES    (BM * ROW_STRIDE)      // 31232 (dynamic smem)

#define F_STRIDE_H 40                     // f_s row stride in halves (80B)
#define W_STRIDE_H 24                     // w_s row stride in halves (48B)

__device__ uint4  g_bfrag[4 * NSTEP * 32];
__device__ int    g_rowptr[40001];
__device__ __half g_feat16[NPTS * FDIM];
__device__ float4 g_pts4[NPTS];

__device__ __forceinline__ uint32_t smem_u32(const void* p) {
    uint32_t a;
    asm("{ .reg .u64 t; cvta.to.shared.u64 t, %1; cvt.u32.u64 %0, t; }" : "=r"(a) : "l"(p));
    return a;
}
__device__ __forceinline__ void ldsm4(uint32_t addr, uint32_t* r) {
    asm volatile("ldmatrix.sync.aligned.m8n8.x4.shared.b16 {%0,%1,%2,%3}, [%4];"
                 : "=r"(r[0]), "=r"(r[1]), "=r"(r[2]), "=r"(r[3]) : "r"(addr));
}
__device__ __forceinline__ void ldsm4t(uint32_t addr, uint32_t* r) {
    asm volatile("ldmatrix.sync.aligned.m8n8.x4.trans.shared.b16 {%0,%1,%2,%3}, [%4];"
                 : "=r"(r[0]), "=r"(r[1]), "=r"(r[2]), "=r"(r[3]) : "r"(addr));
}
__device__ __forceinline__ void mma16816h(float* d, const uint32_t* a,
                                          uint32_t b0, uint32_t b1) {
    asm volatile(
        "mma.sync.aligned.m16n8k16.row.col.f32.f16.f16.f32 "
        "{%0,%1,%2,%3}, {%4,%5,%6,%7}, {%8,%9}, {%0,%1,%2,%3};"
        : "+f"(d[0]), "+f"(d[1]), "+f"(d[2]), "+f"(d[3])
        : "r"(a[0]), "r"(a[1]), "r"(a[2]), "r"(a[3]), "r"(b0), "r"(b1));
}
__device__ __forceinline__ void cpa16(uint32_t dst, const void* src) {
    asm volatile("cp.async.ca.shared.global [%0], [%1], 16;" :: "r"(dst), "l"(src));
}

// ================= prep: bfrag + feat16 + pts4 + rowptr =================
__global__ void prep_kernel(const float* __restrict__ kv,
                            const float* __restrict__ features,
                            const float* __restrict__ points,
                            const int* __restrict__ sid,
                            int E, int M, int NF,
                            int nf16_blocks, int pts_blocks) {
    int b = blockIdx.x;
    int t = threadIdx.x;
    if (b == 0) {
        for (int i = t; i < 4 * NSTEP * 32; i += 256) {
            int l  = i & 31;
            int s  = (i >> 5) % NSTEP;
            int wn = i / (NSTEP * 32);
            int n0 = wn * 16 + (l >> 2);
            int kb = s * 16 + 2 * (l & 3);
            auto h2 = [&](int n, int k) -> uint32_t {
                __half2 p = __halves2half2(__float2half_rn(kv[k * CDIM + n]),
                                           __float2half_rn(kv[(k + 1) * CDIM + n]));
                return *(uint32_t*)&p;
            };
            uint4 v;
            v.x = h2(n0,     kb);
            v.y = h2(n0 + 8, kb);
            v.z = h2(n0,     kb + 8);
            v.w = h2(n0 + 8, kb + 8);
            g_bfrag[i] = v;
        }
    } else if (b <= nf16_blocks) {
        int i4 = ((b - 1) * 256 + t) * 4;
        if (i4 < NF) {
            float4 v = *(const float4*)(features + i4);
            __half2 h0 = __floats2half2_rn(v.x, v.y);
            __half2 h1 = __floats2half2_rn(v.z, v.w);
            *(uint2*)(g_feat16 + i4) = make_uint2(*(uint32_t*)&h0, *(uint32_t*)&h1);
        }
    } else if (b <= nf16_blocks + pts_blocks) {
        int i = (b - 1 - nf16_blocks) * 256 + t;
        if (i < NPTS)
            g_pts4[i] = make_float4(points[i * 3], points[i * 3 + 1],
                                    points[i * 3 + 2], 0.f);
    } else {
        int i = (b - 1 - nf16_blocks - pts_blocks) * 256 + t;
        if (i >= E) return;
        int s  = __ldg(sid + i);
        int sp = (i == 0) ? -1 : __ldg(sid + i - 1);
        for (int m = sp + 1; m <= s; m++) g_rowptr[m] = i;
        if (i == E - 1)
            for (int m = s + 1; m <= M; m++) g_rowptr[m] = E;
    }
}

// ================= main: fused agg(MMA) + GEMM =================
__global__ __launch_bounds__(THREADS, 3) void kpconv_main_kernel(
    const float* __restrict__ outp,
    const int*   __restrict__ nbr,
    const float* __restrict__ kpts,
    float*       __restrict__ out,
    int M)
{
    extern __shared__ __align__(128) char sm[];         // A tile [32][976B]
    __shared__ __half w_s[8][16 * W_STRIDE_H];          // per-warp W[e][k], 48B stride
    __shared__ __half f_s[8][16 * F_STRIDE_H];          // per-warp F[e][f], 80B stride

    const uint32_t sbase = smem_u32(sm);
    const int tid  = threadIdx.x;
    const int warp = tid >> 5;
    const int lane = tid & 31;
    const int m0   = blockIdx.x * BM;

    const int eidx  = lane & 15;          // edge for this lane
    const int khalf = lane >> 4;          // 0: k0-7, 1: k8-15

    // kernel-point constants in registers (row/batch-invariant)
    float4 kq[8];
    #pragma unroll
    for (int kk = 0; kk < 8; kk++) {
        int k = khalf * 8 + kk;
        if (k < KP) {
            float x = __ldg(kpts + k * 3 + 0);
            float y = __ldg(kpts + k * 3 + 1);
            float z = __ldg(kpts + k * 3 + 2);
            kq[kk] = make_float4(x, y, z, fmaf(x, x, fmaf(y, y, z * z)));
        } else {
            kq[kk] = make_float4(0.f, 0.f, 0.f, 1.0e6f);   // k15 -> w = 0
        }
    }

    // zero this warp's feature tile (stale-data protection for partial batches)
    {
        uint4* fz = (uint4*)&f_s[warp][0];
        #pragma unroll
        for (int i = 0; i < 3; i++) {
            int idx = lane + i * 32;
            if (idx < 16 * F_STRIDE_H / 8) fz[idx] = make_uint4(0, 0, 0, 0);
        }
    }
    __syncwarp();

    const uint32_t wbase = smem_u32(&w_s[warp][0]);
    const uint32_t fbase = smem_u32(&f_s[warp][0]);

    // ldmatrix lane addressing (R13-validated mapping, padded strides)
    const int g  = lane >> 3;
    const int lr = lane & 7;
    const uint32_t a_addr = wbase + (uint32_t)(lr + ((g >> 1) << 3)) * (W_STRIDE_H * 2)
                          + (uint32_t)((g & 1) << 3) * 2;
    const uint32_t b_addr = fbase + (uint32_t)(lr + ((g & 1) << 3)) * (F_STRIDE_H * 2)
                          + (uint32_t)((g >> 1) << 3) * 2;

    // ---------------- Phase A: aggregation via MMA, 4 rows per warp ----------------
    #pragma unroll
    for (int rr = 0; rr < 4; rr++) {
        const int r = warp + rr * 8;
        const int m = m0 + r;
        if (m < M) {
            int s = __ldg(g_rowptr + m);
            int e = __ldg(g_rowptr + m + 1);

            float ox = __ldg(outp + m * 3 + 0);
            float oy = __ldg(outp + m * 3 + 1);
            float oz = __ldg(outp + m * 3 + 2);

            float ca[4][4];
            #pragma unroll
            for (int nb = 0; nb < 4; nb++)
                #pragma unroll
                for (int i = 0; i < 4; i++) ca[nb][i] = 0.f;

            for (int base = s; base < e; base += 16) {
                int rem = e - base;
                int cnt = rem < 16 ? rem : 16;
                bool valid = (eidx < cnt);

                // nbr + point via float4 table (1 LDG.128)
                int my_ni = 0;
                float px = 0.f, py = 0.f, pz = 0.f;
                if (valid) {
                    my_ni = __ldg(nbr + base + eidx);
                    float4 p = __ldg(&g_pts4[my_ni]);
                    px = p.x; py = p.y; pz = p.z;
                }

                // feature cp.async: lane's own edge, 2 chunks of 16B (80B rows)
                if (valid) {
                    const __half* srcf = g_feat16 + (size_t)my_ni * FDIM;
                    uint32_t dstf = fbase + (uint32_t)eidx * (F_STRIDE_H * 2)
                                  + (uint32_t)khalf * 16;
                    cpa16(dstf,      srcf + khalf * 8);
                    cpa16(dstf + 32, srcf + 16 + khalf * 8);
                }
                asm volatile("cp.async.commit_group;");

                // ---- weight phase: 8 k-points per lane (expanded dot, kq regs) ----
                float rx = px - ox, ry = py - oy, rz = pz - oz;
                float relsq = fmaf(rx, rx, fmaf(ry, ry, rz * rz));
                float w[8];
                #pragma unroll
                for (int kk = 0; kk < 8; kk++) {
                    float4 q = kq[kk];
                    float d  = fmaf(rx, q.x, fmaf(ry, q.y, rz * q.z));
                    float sq = fmaxf(fmaf(-2.f, d, relsq + q.w), 0.f);
                    float wv = fmaxf(fmaf(sqrtf(sq), -INV_EXTENT, 1.f), 0.f);
                    w[kk] = valid ? wv : 0.f;
                }
                __half2 h0 = __floats2half2_rn(w[0], w[1]);
                __half2 h1 = __floats2half2_rn(w[2], w[3]);
                __half2 h2 = __floats2half2_rn(w[4], w[5]);
                __half2 h3 = __floats2half2_rn(w[6], w[7]);
                *(uint4*)(w_s[warp] + eidx * W_STRIDE_H + khalf * 8) =
                    make_uint4(*(uint32_t*)&h0, *(uint32_t*)&h1,
                               *(uint32_t*)&h2, *(uint32_t*)&h3);
                __syncwarp();

                // A fragment (W^T)
                uint32_t a[4];
                ldsm4t(a_addr, a);

                // features ready
                asm volatile("cp.async.wait_group 0;");
                __syncwarp();

                uint32_t b0[4], b1[4];
                ldsm4t(b_addr,      b0);    // f 0..15
                ldsm4t(b_addr + 32, b1);    // f 16..31

                mma16816h(ca[0], a, b0[0], b0[1]);
                mma16816h(ca[1], a, b0[2], b0[3]);
                mma16816h(ca[2], a, b1[0], b1[1]);
                mma16816h(ca[3], a, b1[2], b1[3]);
            }

            // flush agg fragments -> fp16 A-tile row (kk = kp*32 + f)
            char* ar = sm + r * ROW_STRIDE;
            const int kp1 = lane >> 2;
            const int f0  = (lane & 3) * 2;
            #pragma unroll
            for (int nb = 0; nb < 4; nb++) {
                int f = nb * 8 + f0;
                __half2 hA = __floats2half2_rn(ca[nb][0], ca[nb][1]);
                *(__half2*)(ar + (kp1 * 32 + f) * 2) = hA;
                if (kp1 < 7) {
                    __half2 hB = __floats2half2_rn(ca[nb][2], ca[nb][3]);
                    *(__half2*)(ar + ((kp1 + 8) * 32 + f) * 2) = hB;
                }
            }
        }
    }
    __syncthreads();

    // ---------------- Phase B: GEMM [32,480] x [64,480]^T (unchanged) ----------------
    const int warp_m = warp & 1;
    const int warp_n = warp >> 1;
    const uint32_t abase = sbase + (uint32_t)(warp_m * 16 + (lane & 15)) * ROW_STRIDE
                         + (uint32_t)(lane >> 4) * 16;
    const uint4* bf = g_bfrag + (size_t)warp_n * NSTEP * 32 + lane;

    float acc[2][4];
    #pragma unroll
    for (int nt = 0; nt < 2; nt++)
        #pragma unroll
        for (int i = 0; i < 4; i++) acc[nt][i] = 0.f;

    #pragma unroll
    for (int s = 0; s < NSTEP; s++) {
        uint32_t a[4];
        ldsm4(abase + (uint32_t)s * 32, a);
        uint4 f = __ldg(bf + s * 32);
        mma16816h(acc[0], a, f.x, f.z);
        mma16816h(acc[1], a, f.y, f.w);
    }

    const int qr = lane >> 2;
    const int qc = (lane & 3) * 2;
    #pragma unroll
    for (int nt = 0; nt < 2; nt++) {
        int r0 = m0 + warp_m * 16 + qr;
        int cc = warp_n * 16 + nt * 8 + qc;
        if (r0 < M)
            *(float2*)(out + (size_t)r0 * CDIM + cc) = make_float2(acc[nt][0], acc[nt][1]);
        if (r0 + 8 < M)
            *(float2*)(out + (size_t)(r0 + 8) * CDIM + cc) = make_float2(acc[nt][2], acc[nt][3]);
    }
}

// ================= launch =================
extern "C" void kernel_launch(void* const* d_in, const int* in_sizes, int n_in,
                              void* d_out, int out_size) {
    const float* points   = (const float*)d_in[0];
    const float* features = (const float*)d_in[1];
    const float* outp     = (const float*)d_in[2];
    const int*   nbr      = (const int*)d_in[3];
    const int*   sid      = (const int*)d_in[4];
    const float* kpts     = (const float*)d_in[5];
    const float* kv       = (const float*)d_in[6];
    float*       out      = (float*)d_out;

    int E  = in_sizes[3];
    int NF = in_sizes[1];
    int M  = out_size / CDIM;

    static bool attr_set = false;
    if (!attr_set) {
        cudaFuncSetAttribute(kpconv_main_kernel,
                             cudaFuncAttributeMaxDynamicSharedMemorySize,
                             A_BYTES);
        attr_set = true;
    }

    int nf16_blocks = (NF / 4 + 255) / 256;
    int pts_blocks  = (NPTS + 255) / 256;
    int prep_blocks = 1 + nf16_blocks + pts_blocks + (E + 255) / 256;
    prep_kernel<<<prep_blocks, 256>>>(kv, features, points, sid, E, M, NF,
                                      nf16_blocks, pts_blocks);
    int blocks = (M + BM - 1) / BM;
    kpconv_main_kernel<<<blocks, THREADS, A_BYTES>>>(outp, nbr, kpts, out, M);
}